// round 1
// baseline (speedup 1.0000x reference)
#include <cuda_runtime.h>
#include <math.h>

#define BATCH 32
#define INC 3
#define OUTC 64
#define IMG 64
#define PH 32
#define NL 16
#define LEAFW 128
#define OUTW 100

// Scratch (static __device__ — no allocations allowed)
__device__ float g_h1[NL * BATCH * OUTC * PH * PH];   // 134 MB: conv1+pool+relu output
__device__ float g_feat[NL * BATCH * OUTC];
__device__ float g_scores[BATCH * 4];
__device__ float g_mix[BATCH * NL];
__device__ float g_logits[NL * BATCH * OUTW];

// ---------------------------------------------------------------------------
// Routing: for depth d, conv x with single filter node_weights[2^(d+1)-2],
// take max over all (H,W) positions -> g_scores[b][d]
// ---------------------------------------------------------------------------
__global__ void k_route(const float* __restrict__ x, const float* __restrict__ nw) {
    int b = blockIdx.x;
    int d = blockIdx.y;
    int t = threadIdx.x;  // 256

    __shared__ float sw_[INC * 25];
    __shared__ float red[256];

    const float* w = nw + ((2 << d) - 2) * INC * 25;
    for (int i = t; i < INC * 25; i += 256) sw_[i] = w[i];
    __syncthreads();

    const float* xb = x + (long)b * INC * IMG * IMG;
    float m = -1e30f;
    for (int p = t; p < IMG * IMG; p += 256) {
        int y = p >> 6, xx = p & 63;
        float s = 0.f;
        #pragma unroll
        for (int c = 0; c < INC; c++) {
            #pragma unroll
            for (int ky = 0; ky < 5; ky++) {
                int iy = y + ky - 2;
                if (iy < 0 || iy >= IMG) continue;
                #pragma unroll
                for (int kx = 0; kx < 5; kx++) {
                    int ix = xx + kx - 2;
                    if (ix < 0 || ix >= IMG) continue;
                    s += __ldg(&xb[(c << 12) + (iy << 6) + ix]) * sw_[c * 25 + ky * 5 + kx];
                }
            }
        }
        m = fmaxf(m, s);
    }
    red[t] = m;
    __syncthreads();
    for (int s = 128; s > 0; s >>= 1) {
        if (t < s) red[t] = fmaxf(red[t], red[t + s]);
        __syncthreads();
    }
    if (t == 0) g_scores[b * 4 + d] = red[0];
}

// ---------------------------------------------------------------------------
// Mixture weights from scores + per-node biases
// ---------------------------------------------------------------------------
__global__ void k_mix(const float* __restrict__ nb) {
    int t = threadIdx.x;
    if (t >= BATCH * NL) return;
    int b = t >> 4, l = t & 15;
    float m = 1.f;
    #pragma unroll
    for (int d = 0; d < 4; d++) {
        int j = l >> (4 - d);
        int bit = (l >> (3 - d)) & 1;
        float z = g_scores[b * 4 + d] + nb[(1 << d) - 1 + j];
        float be = 1.f / (1.f + expf(-z));
        m *= bit ? be : (1.f - be);
    }
    g_mix[b * NL + l] = m;
}

// ---------------------------------------------------------------------------
// conv1 (3->64, 5x5, SAME) + maxpool2 + relu  ->  g_h1[l][b][oc][32][32]
// grid: (l*32+b, og in 0..3, ytile in 0..1); block 256
// Each thread: one out channel (of 16 in the group), 2 pooled columns, 16 pooled rows.
// Shared: input y-slab with halo (3 x 36 x 68) + 16 filters
// ---------------------------------------------------------------------------
__global__ void __launch_bounds__(256) k_conv1(const float* __restrict__ x,
                                               const float* __restrict__ cw1) {
    __shared__ float sx[INC][36][68];      // 29.4 KB
    __shared__ float sw_[16 * INC * 25];   // 4.8 KB

    int lb = blockIdx.x;
    int l = lb >> 5, b = lb & 31;
    int og = blockIdx.y;       // out-channel group of 16
    int yt = blockIdx.z;       // y tile (pooled rows 16*yt .. 16*yt+15)
    int t = threadIdx.x;

    // load input slab with zero halo
    for (int idx = t; idx < INC * 36 * 68; idx += 256) {
        int c = idx / (36 * 68);
        int rem = idx % (36 * 68);
        int yy = rem / 68, xx = rem % 68;
        int gy = yt * 32 + yy - 2, gx = xx - 2;
        float v = 0.f;
        if (gy >= 0 && gy < IMG && gx >= 0 && gx < IMG)
            v = x[(((long)b * INC + c) * IMG + gy) * IMG + gx];
        sx[c][yy][xx] = v;
    }
    // load 16 filters
    for (int idx = t; idx < 16 * INC * 25; idx += 256) {
        int oc_l = idx / (INC * 25);
        int rem = idx % (INC * 25);
        sw_[idx] = cw1[(((long)l * OUTC + og * 16 + oc_l) * INC) * 25 + rem];
    }
    __syncthreads();

    int oc_l = t >> 4;
    int lane16 = t & 15;
    int oc = og * 16 + oc_l;

    #pragma unroll 1
    for (int ps = 0; ps < 2; ps++) {
        int pc = lane16 + ps * 16;    // pooled column 0..31
        #pragma unroll 1
        for (int py = 0; py < 16; py++) {
            float a00 = 0.f, a01 = 0.f, a10 = 0.f, a11 = 0.f;
            #pragma unroll
            for (int c = 0; c < INC; c++) {
                float win[6][6];
                #pragma unroll
                for (int r = 0; r < 6; r++)
                    #pragma unroll
                    for (int q = 0; q < 6; q++)
                        win[r][q] = sx[c][2 * py + r][2 * pc + q];
                const float* wp = &sw_[(oc_l * INC + c) * 25];
                #pragma unroll
                for (int ky = 0; ky < 5; ky++)
                    #pragma unroll
                    for (int kx = 0; kx < 5; kx++) {
                        float wv = wp[ky * 5 + kx];
                        a00 = fmaf(win[ky][kx], wv, a00);
                        a01 = fmaf(win[ky][kx + 1], wv, a01);
                        a10 = fmaf(win[ky + 1][kx], wv, a10);
                        a11 = fmaf(win[ky + 1][kx + 1], wv, a11);
                    }
            }
            float v = fmaxf(fmaxf(a00, a01), fmaxf(a10, a11));
            v = fmaxf(v, 0.f);
            int prow = yt * 16 + py;
            g_h1[((((long)l * BATCH + b) * OUTC + oc) * PH + prow) * PH + pc] = v;
        }
    }
}

// ---------------------------------------------------------------------------
// conv2 (64->64, 5x5, SAME on 32x32) + relu + global spatial max -> g_feat
// grid: (l*32+b, og in 0..7); block 256 (8 warps, one out channel each).
// lane = output column (32). 32 row accumulators/thread, sliding 5-row window,
// weights hoisted to 25 registers per input channel. 8 input-channel chunks of 8.
// ---------------------------------------------------------------------------
#define ICC 8
__global__ void __launch_bounds__(256, 2) k_conv2(const float* __restrict__ cw2) {
    __shared__ float sin_[ICC][36][36];    // 41.5 KB
    __shared__ float sw_[8][ICC][25];      // 6.4 KB

    int lb = blockIdx.x;
    int l = lb >> 5, b = lb & 31;
    int og = blockIdx.y;
    int t = threadIdx.x;
    int warp = t >> 5, lane = t & 31;
    int oc = og * 8 + warp;

    float acc[32];
    #pragma unroll
    for (int i = 0; i < 32; i++) acc[i] = 0.f;

    const float* h1base = &g_h1[(((long)l * BATCH + b) * OUTC) * PH * PH];

    #pragma unroll 1
    for (int cc = 0; cc < 8; cc++) {
        __syncthreads();   // previous iteration's consumers done
        // load input chunk (8 channels) with zero halo
        for (int idx = t; idx < ICC * 36 * 36; idx += 256) {
            int c = idx / 1296;
            int rem = idx % 1296;
            int yy = rem / 36, xx = rem % 36;
            int gy = yy - 2, gx = xx - 2;
            float v = 0.f;
            if (gy >= 0 && gy < PH && gx >= 0 && gx < PH)
                v = h1base[((cc * ICC + c) * PH + gy) * PH + gx];
            sin_[c][yy][xx] = v;
        }
        // load weights: 8 oc x 8 ic x 25
        for (int idx = t; idx < 8 * ICC * 25; idx += 256) {
            int w8 = idx / (ICC * 25);
            int rem = idx % (ICC * 25);
            int ic = rem / 25, kk = rem % 25;
            sw_[w8][ic][kk] =
                cw2[(((long)l * OUTC + og * 8 + w8) * OUTC + cc * ICC + ic) * 25 + kk];
        }
        __syncthreads();

        #pragma unroll 1
        for (int ic = 0; ic < ICC; ic++) {
            float wr[25];
            #pragma unroll
            for (int k = 0; k < 25; k++) wr[k] = sw_[warp][ic][k];

            float win[5][5];  // rows cycle mod 5; cols lane..lane+4
            #pragma unroll
            for (int r = 0; r < 4; r++)
                #pragma unroll
                for (int q = 0; q < 5; q++)
                    win[r][q] = sin_[ic][r][lane + q];

            #pragma unroll
            for (int y = 0; y < 32; y++) {
                int rl = (y + 4) % 5;
                #pragma unroll
                for (int q = 0; q < 5; q++)
                    win[rl][q] = sin_[ic][y + 4][lane + q];
                float a = acc[y];
                #pragma unroll
                for (int ky = 0; ky < 5; ky++) {
                    int rs = (y + ky) % 5;
                    #pragma unroll
                    for (int kx = 0; kx < 5; kx++)
                        a = fmaf(win[rs][kx], wr[ky * 5 + kx], a);
                }
                acc[y] = a;
            }
        }
    }

    // relu + spatial max: relu(h).max == max(max(h), 0)
    float m = -1e30f;
    #pragma unroll
    for (int i = 0; i < 32; i++) m = fmaxf(m, acc[i]);
    m = fmaxf(m, 0.f);
    #pragma unroll
    for (int off = 16; off > 0; off >>= 1)
        m = fmaxf(m, __shfl_xor_sync(0xffffffffu, m, off));
    if (lane == 0) g_feat[((long)l * BATCH + b) * OUTC + oc] = m;
}

// ---------------------------------------------------------------------------
// Per-leaf MLP: logits = (feat @ w1 + b1) @ w2 + b2
// ---------------------------------------------------------------------------
__global__ void k_mlp(const float* __restrict__ w1, const float* __restrict__ b1,
                      const float* __restrict__ w2, const float* __restrict__ b2) {
    int lb = blockIdx.x;
    int l = lb >> 5, b = lb & 31;
    int t = threadIdx.x;  // 128

    __shared__ float sfeat[OUTC];
    __shared__ float shid[LEAFW];

    if (t < OUTC) sfeat[t] = g_feat[((long)l * BATCH + b) * OUTC + t];
    __syncthreads();

    float h = b1[l * LEAFW + t];
    #pragma unroll 8
    for (int k = 0; k < OUTC; k++)
        h = fmaf(sfeat[k], w1[((long)l * OUTC + k) * LEAFW + t], h);
    shid[t] = h;
    __syncthreads();

    if (t < OUTW) {
        float o = b2[l * OUTW + t];
        #pragma unroll 8
        for (int j = 0; j < LEAFW; j++)
            o = fmaf(shid[j], w2[((long)l * LEAFW + j) * OUTW + t], o);
        g_logits[((long)l * BATCH + b) * OUTW + t] = o;
    }
}

// ---------------------------------------------------------------------------
// Final mixture: out[b][o] = sum_l logits[l][b][o] * mix[b][l]
// ---------------------------------------------------------------------------
__global__ void k_final(float* __restrict__ out) {
    int b = blockIdx.x;
    int t = threadIdx.x;
    if (t < OUTW) {
        float s = 0.f;
        #pragma unroll
        for (int l = 0; l < NL; l++)
            s = fmaf(g_logits[((long)l * BATCH + b) * OUTW + t], g_mix[b * NL + l], s);
        out[b * OUTW + t] = s;
    }
}

// ---------------------------------------------------------------------------
extern "C" void kernel_launch(void* const* d_in, const int* in_sizes, int n_in,
                              void* d_out, int out_size) {
    const float* x   = (const float*)d_in[0];
    const float* nw  = (const float*)d_in[1];
    const float* nb  = (const float*)d_in[2];
    const float* cw1 = (const float*)d_in[3];
    const float* cw2 = (const float*)d_in[4];
    const float* w1  = (const float*)d_in[5];
    const float* b1  = (const float*)d_in[6];
    const float* w2  = (const float*)d_in[7];
    const float* b2  = (const float*)d_in[8];
    float* out = (float*)d_out;

    k_route<<<dim3(BATCH, 4), 256>>>(x, nw);
    k_mix<<<1, 512>>>(nb);
    k_conv1<<<dim3(NL * BATCH, 4, 2), 256>>>(x, cw1);
    k_conv2<<<dim3(NL * BATCH, 8), 256>>>(cw2);
    k_mlp<<<NL * BATCH, 128>>>(w1, b1, w2, b2);
    k_final<<<BATCH, 128>>>(out);
}